// round 4
// baseline (speedup 1.0000x reference)
#include <cuda_runtime.h>
#include <math.h>

#define FULLMASK 0xffffffffu

// Composed register-bit CNOT relabel (wires 5..9 = reg bits 0..4), per layer:
// src bits = (r0, r1^r0, r2^r1^r0, r3^r2, r4^r3^r2)   [verified round 1->2]
#define RSRC(r) ( ((r)&1) \
    | (((((r)>>1)^(r))&1)<<1) \
    | (((((r)>>2)^((r)>>1)^(r))&1)<<2) \
    | (((((r)>>3)^((r)>>2))&1)<<3) \
    | (((((r)>>4)^((r)>>3)^((r)>>2))&1)<<4) )

// Frame-tracked lane-wire constants (derived from A_k = (Mrev^-1)^k, verified):
// RY shfl_xor masks m[k][w] = column w of A_k^-1
__device__ __constant__ const int MK[6][5] = {
    { 3,14,12,24,16},
    {13,26,20, 8,16},
    {23, 6,28,24,16},
    {17, 2, 4, 8,16},
    {19,14,12,24,16},
    {29,26,20, 8,16}
};
// RY sign masks s[k][w] = row w of A_k  (logical bit w = parity(lane & mask))
__device__ __constant__ const int SK[6][5] = {
    {1,3,7,12,28},
    {1,2,5,11,23},
    {1,3,6,14,25},
    {1,2,4,8,17},
    {1,3,7,12,29},
    {1,2,5,11,22}
};
// Mixed CNOT(4,5) control mask per layer = row4 of A_{k-1}
__device__ __constant__ const int CK[6] = {16,28,23,25,17,29};
// Measurement broadcast lanes = rows of A_6
__device__ __constant__ const int MROW[5] = {1,2,5,11,22};

__device__ __forceinline__ float fast_tanh(float x) {
    float e;
    asm("ex2.approx.f32 %0, %1;" : "=f"(e) : "f"(x * 2.88539008177792681f));
    return (e - 1.0f) * __frcp_rn(e + 1.0f);
}

__global__ __launch_bounds__(128, 8)
void dq_kernel(const float* __restrict__ x,
               const float* __restrict__ W1,
               const float* __restrict__ b1,
               const float* __restrict__ qw,
               const float* __restrict__ W2,
               const float* __restrict__ b2,
               float* __restrict__ out)
{
    __shared__ alignas(16) float sW1[10][512];   // W1 transposed: [q][d]
    __shared__ float sW2[640];       // [10][64]
    __shared__ float sb2[64];
    __shared__ float sb1[10];
    __shared__ float sqt[6][10];     // tan(theta/2)
    __shared__ float sC[6];          // prod of 10 cos per layer
    __shared__ float scc[64];

    const int tid = threadIdx.x;

    // ---- stage weights ----
#pragma unroll 8
    for (int i = tid; i < 5120; i += 128) {
        int d = i / 10, q = i - d * 10;
        sW1[q][d] = W1[i];
    }
    for (int i = tid; i < 640; i += 128) sW2[i] = W2[i];
    if (tid < 64) sb2[tid] = b2[tid];
    if (tid < 10) sb1[tid] = b1[tid];
    if (tid < 60) {
        float th = 0.5f * qw[tid];
        float s = __sinf(th), c = __cosf(th);
        sqt[tid / 10][tid % 10] = s * __frcp_rn(c);
        scc[tid] = c;
    }
    __syncthreads();
    if (tid < 6) {
        float p = 1.f;
#pragma unroll
        for (int w = 0; w < 10; w++) p *= scc[tid * 10 + w];
        sC[tid] = p;
    }
    __syncthreads();

    const int warp = tid >> 5;
    const int lane = tid & 31;
    const int sample = blockIdx.x * 4 + warp;
    const float* xr = x + (size_t)sample * 512;

    // ---- angles = tanh(x@W1 + b1) * pi/2; per-wire u/v ----
    const float4* x4 = (const float4*)xr;
    float4 xv[4];
#pragma unroll
    for (int t = 0; t < 4; t++) xv[t] = x4[lane + 32 * t];

    float u[10], v[10];
#pragma unroll
    for (int q = 0; q < 10; q++) {
        const float4* w4 = (const float4*)(&sW1[q][0]);
        float p = 0.f;
#pragma unroll
        for (int t = 0; t < 4; t++) {
            float4 wv = w4[lane + 32 * t];
            p = fmaf(xv[t].x, wv.x, p);
            p = fmaf(xv[t].y, wv.y, p);
            p = fmaf(xv[t].z, wv.z, p);
            p = fmaf(xv[t].w, wv.w, p);
        }
#pragma unroll
        for (int off = 16; off; off >>= 1) p += __shfl_xor_sync(FULLMASK, p, off);
        float ang = fast_tanh(p + sb1[q]) * 1.57079632679489662f;
        float hh = 0.5f * ang;
        float sn = __sinf(hh), cs = __cosf(hh);
        u[q] = (cs - sn) * 0.70710678118654752f;
        v[q] = (cs + sn) * 0.70710678118654752f;
    }

    // ---- build product state (frame = identity here) ----
    float st[32];
    float L = 1.f;
#pragma unroll
    for (int w = 0; w < 5; w++) L *= ((lane >> w) & 1) ? v[w] : u[w];
    st[0] = L;
#pragma unroll
    for (int b = 0; b < 5; b++) {
        const int m = 1 << b;
        const int w = 5 + b;
#pragma unroll
        for (int r = 0; r < 32; r++) {
            if (r < m) {
                st[r + m] = st[r] * v[w];
                st[r]     = st[r] * u[w];
            }
        }
    }

    // ---- 6 layers; lane-CNOTs absorbed into per-layer masks (NO perm shfl) ----
#pragma unroll
    for (int k = 0; k < 6; k++) {
        // (1) mixed CNOT(4,5): ctrl = logical wire-4 bit = parity(lane & CK[k])
        {
            const bool qsw = (__popc(lane & CK[k]) & 1);
#pragma unroll
            for (int i = 0; i < 16; i++) {
                float a = st[2 * i], b = st[2 * i + 1];
                st[2 * i]     = qsw ? b : a;
                st[2 * i + 1] = qsw ? a : b;
            }
        }
        // (2) all reg CNOTs: free compile-time relabel
        {
            float tp[32];
#pragma unroll
            for (int r = 0; r < 32; r++) tp[r] = st[RSRC(r)];
#pragma unroll
            for (int r = 0; r < 32; r++) st[r] = tp[r];
        }
        // (3) RY on lane wires in the transformed frame, cosine deferred
#pragma unroll
        for (int w = 0; w < 5; w++) {
            const int m = MK[k][w];
            const float t = sqt[k][w];
            float tq = (__popc(lane & SK[k][w]) & 1) ? t : -t;
#pragma unroll
            for (int r = 0; r < 32; r++) {
                float o = __shfl_xor_sync(FULLMASK, st[r], m);
                st[r] = fmaf(tq, o, st[r]);
            }
        }
        // (4) RY on reg wires, cosine deferred
#pragma unroll
        for (int b = 0; b < 5; b++) {
            float tw = sqt[k][5 + b];
            const int m = 1 << b;
#pragma unroll
            for (int r = 0; r < 32; r++) {
                if ((r & m) == 0) {
                    float a0 = st[r], a1 = st[r + m];
                    st[r]     = fmaf(-tw, a1, a0);
                    st[r + m] = fmaf( tw, a0, a1);
                }
            }
        }
        // (5) deferred cosines
        {
            float Ck = sC[k];
#pragma unroll
            for (int r = 0; r < 32; r++) st[r] *= Ck;
        }
    }

    // ---- measurement ----
    float T = 0.f;
#pragma unroll
    for (int r = 0; r < 32; r++) {
        st[r] = st[r] * st[r];
        T += st[r];
    }

    float e[10];
    // lane wires: full signed Walsh-Hadamard over lanes (5 shfl), then pick
    // coefficients at lanes row_w(A6) (5 broadcast shfl)
    {
        float xwh = T;
#pragma unroll
        for (int j = 0; j < 5; j++) {
            float o = __shfl_xor_sync(FULLMASK, xwh, 1 << j);
            xwh = ((lane >> j) & 1) ? (o - xwh) : (xwh + o);
        }
#pragma unroll
        for (int w = 0; w < 5; w++)
            e[w] = __shfl_sync(FULLMASK, xwh, MROW[w]);
    }
    // reg wires 5..9: pair-tree over registers, then lane all-reduce
    {
        float p0[16], p1[8], p2[4], p3[2];
        float d0 = 0.f, d1 = 0.f, d2 = 0.f, d3 = 0.f, d4;
#pragma unroll
        for (int i = 0; i < 16; i++) { p0[i] = st[2*i] + st[2*i+1]; d0 += st[2*i] - st[2*i+1]; }
#pragma unroll
        for (int i = 0; i < 8; i++)  { p1[i] = p0[2*i] + p0[2*i+1]; d1 += p0[2*i] - p0[2*i+1]; }
#pragma unroll
        for (int i = 0; i < 4; i++)  { p2[i] = p1[2*i] + p1[2*i+1]; d2 += p1[2*i] - p1[2*i+1]; }
#pragma unroll
        for (int i = 0; i < 2; i++)  { p3[i] = p2[2*i] + p2[2*i+1]; d3 += p2[2*i] - p2[2*i+1]; }
        d4 = p3[0] - p3[1];
        float dd[5] = {d0, d1, d2, d3, d4};
#pragma unroll
        for (int b = 0; b < 5; b++) {
            float acc = dd[b];
#pragma unroll
            for (int off = 16; off; off >>= 1) acc += __shfl_xor_sync(FULLMASK, acc, off);
            e[5 + b] = acc;
        }
    }

    // ---- out = e @ W2 + b2 ----
#pragma unroll
    for (int t = 0; t < 2; t++) {
        int o = lane + 32 * t;
        float acc = sb2[o];
#pragma unroll
        for (int q = 0; q < 10; q++) acc = fmaf(e[q], sW2[q * 64 + o], acc);
        out[(size_t)sample * 64 + o] = acc;
    }
}

extern "C" void kernel_launch(void* const* d_in, const int* in_sizes, int n_in,
                              void* d_out, int out_size) {
    const float* x  = (const float*)d_in[0];
    const float* W1 = (const float*)d_in[1];
    const float* b1 = (const float*)d_in[2];
    const float* qw = (const float*)d_in[3];
    const float* W2 = (const float*)d_in[4];
    const float* b2 = (const float*)d_in[5];
    float* out = (float*)d_out;

    int B = in_sizes[0] / 512;          // 8192
    int grid = B / 4;                   // 4 samples (warps) per 128-thread block
    dq_kernel<<<grid, 128>>>(x, W1, b1, qw, W2, b2, out);
}

// round 5
// speedup vs baseline: 1.1597x; 1.1597x over previous
#include <cuda_runtime.h>
#include <math.h>

#define FULLMASK 0xffffffffu

// Composed register-bit CNOT relabel (wires 5..9 = reg bits 0..4), per layer:
// src bits = (r0, r1^r0, r2^r1^r0, r3^r2, r4^r3^r2)
#define RSRC(r) ( ((r)&1) \
    | (((((r)>>1)^(r))&1)<<1) \
    | (((((r)>>2)^((r)>>1)^(r))&1)<<2) \
    | (((((r)>>3)^((r)>>2))&1)<<3) \
    | (((((r)>>4)^((r)>>3)^((r)>>2))&1)<<4) )

// Frame-tracked lane-wire constants (A_k = (Mrev^-1)^k, verified in round 4):
__device__ __constant__ const int MK[6][5] = {
    { 3,14,12,24,16},
    {13,26,20, 8,16},
    {23, 6,28,24,16},
    {17, 2, 4, 8,16},
    {19,14,12,24,16},
    {29,26,20, 8,16}
};
__device__ __constant__ const int SK[6][5] = {
    {1,3,7,12,28},
    {1,2,5,11,23},
    {1,3,6,14,25},
    {1,2,4,8,17},
    {1,3,7,12,29},
    {1,2,5,11,22}
};
__device__ __constant__ const int CK[6] = {16,28,23,25,17,29};
__device__ __constant__ const int MROW[5] = {1,2,5,11,22};

__device__ __forceinline__ float fast_tanh(float x) {
    float e;
    asm("ex2.approx.f32 %0, %1;" : "=f"(e) : "f"(x * 2.88539008177792681f));
    return (e - 1.0f) * __frcp_rn(e + 1.0f);
}

__global__ __launch_bounds__(256)
void dq_kernel(const float* __restrict__ x,
               const float* __restrict__ W1,
               const float* __restrict__ b1,
               const float* __restrict__ qw,
               const float* __restrict__ W2,
               const float* __restrict__ b2,
               float* __restrict__ out)
{
    __shared__ alignas(16) float sW1[10][512];   // W1 transposed: [q][d]
    __shared__ float sW2[640];       // [10][64]
    __shared__ float sb2[64];
    __shared__ float sb1[10];
    __shared__ float sqt[6][10];     // tan(theta/2)
    __shared__ float sCt;            // prod of ALL 60 cos(theta/2)
    __shared__ float scc[64];

    const int tid = threadIdx.x;

    // ---- stage weights ----
#pragma unroll 4
    for (int i = tid; i < 5120; i += 256) {
        int d = i / 10, q = i - d * 10;
        sW1[q][d] = W1[i];
    }
    for (int i = tid; i < 640; i += 256) sW2[i] = W2[i];
    if (tid < 64) sb2[tid] = b2[tid];
    if (tid < 10) sb1[tid] = b1[tid];
    if (tid < 60) {
        float th = 0.5f * qw[tid];
        float s = __sinf(th), c = __cosf(th);
        sqt[tid / 10][tid % 10] = s * __frcp_rn(c);
        scc[tid] = c;
    }
    __syncthreads();
    if (tid == 0) {
        float p = 1.f;
#pragma unroll
        for (int i = 0; i < 60; i++) p *= scc[i];
        sCt = p;
    }
    __syncthreads();

    const int warp = tid >> 5;
    const int lane = tid & 31;
    const int sample = blockIdx.x * 8 + warp;
    const float* xr = x + (size_t)sample * 512;

    // ---- angles = tanh(x@W1 + b1) * pi/2; per-wire u/v ----
    const float4* x4 = (const float4*)xr;
    float4 xv[4];
#pragma unroll
    for (int t = 0; t < 4; t++) xv[t] = x4[lane + 32 * t];

    float u[10], v[10];
#pragma unroll
    for (int q = 0; q < 10; q++) {
        const float4* w4 = (const float4*)(&sW1[q][0]);
        float p = 0.f;
#pragma unroll
        for (int t = 0; t < 4; t++) {
            float4 wv = w4[lane + 32 * t];
            p = fmaf(xv[t].x, wv.x, p);
            p = fmaf(xv[t].y, wv.y, p);
            p = fmaf(xv[t].z, wv.z, p);
            p = fmaf(xv[t].w, wv.w, p);
        }
#pragma unroll
        for (int off = 16; off; off >>= 1) p += __shfl_xor_sync(FULLMASK, p, off);
        float ang = fast_tanh(p + sb1[q]) * 1.57079632679489662f;
        float hh = 0.5f * ang;
        float sn = __sinf(hh), cs = __cosf(hh);
        u[q] = (cs - sn) * 0.70710678118654752f;
        v[q] = (cs + sn) * 0.70710678118654752f;
    }

    // ---- build product state, prescaled by the total deferred cosine ----
    float st[32];
    float L = sCt;   // all 60 trainable-RY cosines folded in up front (linearity)
#pragma unroll
    for (int w = 0; w < 5; w++) L *= ((lane >> w) & 1) ? v[w] : u[w];
    st[0] = L;
#pragma unroll
    for (int b = 0; b < 5; b++) {
        const int m = 1 << b;
        const int w = 5 + b;
#pragma unroll
        for (int r = 0; r < 32; r++) {
            if (r < m) {
                st[r + m] = st[r] * v[w];
                st[r]     = st[r] * u[w];
            }
        }
    }

    // ---- 6 layers; lane-CNOTs absorbed into per-layer masks (frame tracking) ----
#pragma unroll
    for (int k = 0; k < 6; k++) {
        // (1) mixed CNOT(4,5): ctrl = parity(lane & CK[k]); swap reg-bit0 pairs
        {
            const bool qsw = (__popc(lane & CK[k]) & 1);
#pragma unroll
            for (int i = 0; i < 16; i++) {
                float a = st[2 * i], b = st[2 * i + 1];
                st[2 * i]     = qsw ? b : a;
                st[2 * i + 1] = qsw ? a : b;
            }
        }
        // (2) all reg CNOTs: free compile-time relabel
        {
            float tp[32];
#pragma unroll
            for (int r = 0; r < 32; r++) tp[r] = st[RSRC(r)];
#pragma unroll
            for (int r = 0; r < 32; r++) st[r] = tp[r];
        }
        // (3) RY on lane wires in the transformed frame (cosines prescaled)
#pragma unroll
        for (int w = 0; w < 5; w++) {
            const int m = MK[k][w];
            const float t = sqt[k][w];
            float tq = (__popc(lane & SK[k][w]) & 1) ? t : -t;
#pragma unroll
            for (int r = 0; r < 32; r++) {
                float o = __shfl_xor_sync(FULLMASK, st[r], m);
                st[r] = fmaf(tq, o, st[r]);
            }
        }
        // (4) RY on reg wires (cosines prescaled)
#pragma unroll
        for (int b = 0; b < 5; b++) {
            float tw = sqt[k][5 + b];
            const int m = 1 << b;
#pragma unroll
            for (int r = 0; r < 32; r++) {
                if ((r & m) == 0) {
                    float a0 = st[r], a1 = st[r + m];
                    st[r]     = fmaf(-tw, a1, a0);
                    st[r + m] = fmaf( tw, a0, a1);
                }
            }
        }
    }

    // ---- measurement ----
    float T = 0.f;
#pragma unroll
    for (int r = 0; r < 32; r++) {
        st[r] = st[r] * st[r];
        T += st[r];
    }

    float e[10];
    // lane wires: signed WHT over lanes (5 shfl) + 5 broadcasts at rows of A6
    {
        float xwh = T;
#pragma unroll
        for (int j = 0; j < 5; j++) {
            float o = __shfl_xor_sync(FULLMASK, xwh, 1 << j);
            xwh = ((lane >> j) & 1) ? (o - xwh) : (xwh + o);
        }
#pragma unroll
        for (int w = 0; w < 5; w++)
            e[w] = __shfl_sync(FULLMASK, xwh, MROW[w]);
    }
    // reg wires 5..9: pair-tree over registers, then lane all-reduce
    {
        float p0[16], p1[8], p2[4], p3[2];
        float d0 = 0.f, d1 = 0.f, d2 = 0.f, d3 = 0.f, d4;
#pragma unroll
        for (int i = 0; i < 16; i++) { p0[i] = st[2*i] + st[2*i+1]; d0 += st[2*i] - st[2*i+1]; }
#pragma unroll
        for (int i = 0; i < 8; i++)  { p1[i] = p0[2*i] + p0[2*i+1]; d1 += p0[2*i] - p0[2*i+1]; }
#pragma unroll
        for (int i = 0; i < 4; i++)  { p2[i] = p1[2*i] + p1[2*i+1]; d2 += p1[2*i] - p1[2*i+1]; }
#pragma unroll
        for (int i = 0; i < 2; i++)  { p3[i] = p2[2*i] + p2[2*i+1]; d3 += p2[2*i] - p2[2*i+1]; }
        d4 = p3[0] - p3[1];
        float dd[5] = {d0, d1, d2, d3, d4};
#pragma unroll
        for (int b = 0; b < 5; b++) {
            float acc = dd[b];
#pragma unroll
            for (int off = 16; off; off >>= 1) acc += __shfl_xor_sync(FULLMASK, acc, off);
            e[5 + b] = acc;
        }
    }

    // ---- out = e @ W2 + b2 ----
#pragma unroll
    for (int t = 0; t < 2; t++) {
        int o = lane + 32 * t;
        float acc = sb2[o];
#pragma unroll
        for (int q = 0; q < 10; q++) acc = fmaf(e[q], sW2[q * 64 + o], acc);
        out[(size_t)sample * 64 + o] = acc;
    }
}

extern "C" void kernel_launch(void* const* d_in, const int* in_sizes, int n_in,
                              void* d_out, int out_size) {
    const float* x  = (const float*)d_in[0];
    const float* W1 = (const float*)d_in[1];
    const float* b1 = (const float*)d_in[2];
    const float* qw = (const float*)d_in[3];
    const float* W2 = (const float*)d_in[4];
    const float* b2 = (const float*)d_in[5];
    float* out = (float*)d_out;

    int B = in_sizes[0] / 512;          // 8192
    int grid = B / 8;                   // 8 samples (warps) per 256-thread block
    dq_kernel<<<grid, 256>>>(x, W1, b1, qw, W2, b2, out);
}